// round 15
// baseline (speedup 1.0000x reference)
#include <cuda_runtime.h>
#include <cuda_bf16.h>
#include <cuda_fp16.h>
#include <math.h>
#include <stddef.h>
#include <stdint.h>

#define BATCH 8
#define DIM 256
#define P 4096
#define HEADS 8
#define FFI 1024
#define BP 64
#define JTOT 256

__device__ float g_qkv [(size_t)BATCH*768*P];
__device__ float g_comb[(size_t)BATCH*256*P];
__device__ float g_h   [(size_t)BATCH*FFI*P];
__device__ float g_r   [(size_t)BATCH*FFI*P];
__device__ float g_f2  [(size_t)BATCH*DIM*P];
__device__ __half g_wbf [1703936];
__device__ __half g_abf [(size_t)BATCH*P*2048];
__device__ __half g_ks  [(size_t)BP*8192];
__device__ __nv_bfloat16 g_vs [(size_t)BP*16384];
__device__ float g_qp  [BP*32];
__device__ float g_kh  [BP*2048];
__device__ float g_pst [BATCH*P*2];
__device__ float g_cst [BATCH*FFI*2];
__device__ float g_hst [BATCH*FFI*2];
__device__ float g_fst [BATCH*DIM*2];
__device__ float g_hstA[BATCH*FFI*2];
__device__ float g_fstA[BATCH*DIM*2];

__device__ __forceinline__ uint32_t smem_u32(const void* p) {
    uint32_t a;
    asm("{ .reg .u64 t; cvta.to.shared.u64 t, %1; cvt.u32.u64 %0, t; }" : "=r"(a) : "l"(p));
    return a;
}
__device__ __forceinline__ void cp_async16(uint32_t dst, const void* src) {
    asm volatile("cp.async.cg.shared.global [%0], [%1], 16;" :: "r"(dst), "l"(src) : "memory");
}
#define CP_COMMIT() asm volatile("cp.async.commit_group;" ::: "memory")
#define CP_WAIT0()  asm volatile("cp.async.wait_group 0;" ::: "memory")
#define CP_WAIT1()  asm volatile("cp.async.wait_group 1;" ::: "memory")
#define CP_WAIT2()  asm volatile("cp.async.wait_group 2;" ::: "memory")
__device__ __forceinline__ void ldsm_x4(uint32_t* r, uint32_t addr) {
    asm volatile("ldmatrix.sync.aligned.m8n8.x4.shared.b16 {%0,%1,%2,%3}, [%4];"
                 : "=r"(r[0]), "=r"(r[1]), "=r"(r[2]), "=r"(r[3]) : "r"(addr));
}
__device__ __forceinline__ void mma16816h(float* c, const uint32_t* a, const uint32_t* b) {
    asm volatile(
        "mma.sync.aligned.m16n8k16.row.col.f32.f16.f16.f32 "
        "{%0,%1,%2,%3}, {%4,%5,%6,%7}, {%8,%9}, {%0,%1,%2,%3};"
        : "+f"(c[0]), "+f"(c[1]), "+f"(c[2]), "+f"(c[3])
        : "r"(a[0]), "r"(a[1]), "r"(a[2]), "r"(a[3]), "r"(b[0]), "r"(b[1]));
}
__device__ __forceinline__ void mma16816(float* c, const uint32_t* a, const uint32_t* b) {
    asm volatile(
        "mma.sync.aligned.m16n8k16.row.col.f32.bf16.bf16.f32 "
        "{%0,%1,%2,%3}, {%4,%5,%6,%7}, {%8,%9}, {%0,%1,%2,%3};"
        : "+f"(c[0]), "+f"(c[1]), "+f"(c[2]), "+f"(c[3])
        : "r"(a[0]), "r"(a[1]), "r"(a[2]), "r"(a[3]), "r"(b[0]), "r"(b[1]));
}
__device__ __forceinline__ uint32_t packbf2(float a, float b) {
    __nv_bfloat162 h = __floats2bfloat162_rn(a, b);
    return *(uint32_t*)&h;
}
__device__ inline float gelu_exact(float v) {
    return 0.5f * v * (1.0f + erff(v * 0.70710678118654752f));
}

// ---------------- weight split (generalized; dup=1 writes [Whi|Whi]) ----------------
__global__ void w_split_kernel(const float* __restrict__ src, __half* __restrict__ dst,
                               int M, int K, int srcStride, int dstRowStride, int dstColOff,
                               int dup)
{
    int i = blockIdx.x * blockDim.x + threadIdx.x;
    if (i >= M * K) return;
    int m = i / K, k = i - m * K;
    __half hi = __float2half_rn(src[(size_t)m * srcStride + k]);
    size_t row = (size_t)m * dstRowStride + dstColOff;
    dst[row + k] = hi;
    if (dup) dst[row + K + k] = hi;
}

// ---------------- fuse: Wf = Wcl @ w_out, bf = b_comb + Wcl @ b_out ----------------
__global__ void fuse_w_kernel(const float* __restrict__ wcomb, const float* __restrict__ wout,
                              const float* __restrict__ bcomb, const float* __restrict__ bout,
                              float* __restrict__ Wf, float* __restrict__ bf)
{
    int i = blockIdx.x, j = threadIdx.x;
    __shared__ float wrow[256];
    __shared__ float red[256];
    wrow[j] = wcomb[(size_t)i * 512 + j];
    __syncthreads();
    float s = 0.f;
    #pragma unroll 8
    for (int k = 0; k < 256; k++) s += wrow[k] * wout[(size_t)k * 256 + j];
    Wf[(size_t)i * 256 + j] = s;
    red[j] = wrow[j] * bout[j];
    __syncthreads();
    for (int o = 128; o > 0; o >>= 1) {
        if (j < o) red[j] += red[j + o];
        __syncthreads();
    }
    if (j == 0) bf[i] = bcomb[i] + red[0];
}

// ---------------- LN per-pixel stats ----------------
__global__ void ln_stats_kernel(const float* __restrict__ x, float* __restrict__ st)
{
    int idx = blockIdx.x * blockDim.x + threadIdx.x;
    int b = idx >> 12, p = idx & 4095;
    const float* xb = x + (size_t)b * DIM * P + p;
    float s = 0.f, s2 = 0.f;
    #pragma unroll 8
    for (int c = 0; c < DIM; c++) { float v = xb[(size_t)c * P]; s += v; s2 += v * v; }
    float mean = s * (1.f / DIM);
    float var  = s2 * (1.f / DIM) - mean * mean;
    st[idx * 2] = mean; st[idx * 2 + 1] = rsqrtf(var + 1e-5f);
}

// ---------------- transpose+split (writeLo flag, optional LN) ----------------
__global__ void ts_split_kernel(const float* __restrict__ src, __half* __restrict__ dst,
                                int K, int rowStride, int colOff, int writeLo,
                                const float* __restrict__ pst,
                                const float* __restrict__ gamma, const float* __restrict__ beta)
{
    __shared__ float s[32][65];
    int pt = blockIdx.x, kt = blockIdx.y, b = blockIdx.z;
    int t = threadIdx.x;
    const float4* s4 = (const float4*)(src + ((size_t)b * K + kt * 32) * P) + pt * 16;
    int kr = t >> 3, pq = t & 7;
    float4 v0 = s4[(size_t)kr * (P / 4) + pq];
    float4 v1 = s4[(size_t)kr * (P / 4) + pq + 8];
    s[kr][pq*4+0]=v0.x; s[kr][pq*4+1]=v0.y; s[kr][pq*4+2]=v0.z; s[kr][pq*4+3]=v0.w;
    s[kr][32+pq*4+0]=v1.x; s[kr][32+pq*4+1]=v1.y; s[kr][32+pq*4+2]=v1.z; s[kr][32+pq*4+3]=v1.w;
    __syncthreads();
    int pr = t >> 2, ks = t & 3;
    int p = pt * 64 + pr;
    float mean = 0.f, rstd = 1.f;
    if (pst) { mean = pst[((size_t)b*P+p)*2]; rstd = pst[((size_t)b*P+p)*2+1]; }
    __align__(16) __half hi[8];
    __align__(16) __half lo[8];
    #pragma unroll
    for (int i = 0; i < 8; i++) {
        int c = kt * 32 + ks * 8 + i;
        float f = s[ks * 8 + i][pr];
        if (pst) f = (f - mean) * rstd * gamma[c] + beta[c];
        hi[i] = __float2half_rn(f);
        lo[i] = __float2half_rn(f - __half2float(hi[i]));
    }
    __half* dp = dst + ((size_t)b * P + p) * rowStride + colOff + kt * 32 + ks * 8;
    *(uint4*)dp = *(uint4*)hi;
    if (writeLo) *(uint4*)(dp + K) = *(uint4*)lo;
}

// ---------------- gelu(norm(h)) + gelu(norm(r)) -> transposed fp16 (hi only) ------
__global__ void apply_split_kernel(const float* __restrict__ r, const float* __restrict__ h,
                                   const float* __restrict__ str, const float* __restrict__ sth,
                                   __half* __restrict__ dst)
{
    __shared__ float sr[32][65];
    __shared__ float sh[32][65];
    int pt = blockIdx.x, kt = blockIdx.y, b = blockIdx.z;
    int t = threadIdx.x;
    const float4* r4 = (const float4*)(r + ((size_t)b * FFI + kt * 32) * P) + pt * 16;
    const float4* h4 = (const float4*)(h + ((size_t)b * FFI + kt * 32) * P) + pt * 16;
    int kr = t >> 3, pq = t & 7;
    #pragma unroll
    for (int half = 0; half < 2; half++) {
        float4 a = r4[(size_t)kr * (P/4) + pq + half * 8];
        float4 bb = h4[(size_t)kr * (P/4) + pq + half * 8];
        int c0 = half * 32 + pq * 4;
        sr[kr][c0]=a.x; sr[kr][c0+1]=a.y; sr[kr][c0+2]=a.z; sr[kr][c0+3]=a.w;
        sh[kr][c0]=bb.x; sh[kr][c0+1]=bb.y; sh[kr][c0+2]=bb.z; sh[kr][c0+3]=bb.w;
    }
    __syncthreads();
    int pr = t >> 2, ks = t & 3;
    int p = pt * 64 + pr;
    __align__(16) __half hi[8];
    #pragma unroll
    for (int i = 0; i < 8; i++) {
        int c = kt * 32 + ks * 8 + i;
        float mr = str[((size_t)b*FFI+c)*2],  rr = str[((size_t)b*FFI+c)*2+1];
        float mh = sth[((size_t)b*FFI+c)*2],  rh = sth[((size_t)b*FFI+c)*2+1];
        float f = gelu_exact((sh[ks*8+i][pr] - mh) * rh)
                + gelu_exact((sr[ks*8+i][pr] - mr) * rr);
        hi[i] = __float2half_rn(f);
    }
    __half* dp = dst + ((size_t)b * P + p) * 1024 + kt * 32 + ks * 8;
    *(uint4*)dp = *(uint4*)hi;
}

// ---------------- HMMA fp16 GEMM: 32-wide k stages, 4-buffer pipeline ----------------
#define AROWB 80
#define GBUF  10240
#define GEMM_SMEM (8*GBUF)

__global__ void __launch_bounds__(256, 2)
tc_gemm_kernel(const __half* __restrict__ A2, const __half* __restrict__ B2,
               float* __restrict__ C, int K2,
               size_t strideB2, size_t strideC, size_t strideR,
               const float* __restrict__ bias, const float* __restrict__ res,
               float* __restrict__ statA, int l2limit)
{
    extern __shared__ __align__(16) char dyn[];
    const int t = threadIdx.x;
    const int wid = t >> 5, l = t & 31;
    const int n0 = blockIdx.x * 128, m0 = blockIdx.y * 128, bz = blockIdx.z;
    const __half* Bp = B2 + (size_t)bz * strideB2;
    float* Cp = C + (size_t)bz * strideC;
    const float* Rp = res ? res + (size_t)bz * strideR : nullptr;
    const int S = K2 / 32;
    const int wm0 = (wid & 3) * 32, wn0 = (wid >> 2) * 64;
    uint32_t base = smem_u32(dyn);
    const uint32_t aLane = (uint32_t)((wm0 + (l & 15)) * AROWB + (l >> 4) * 16);
    const uint32_t bLane = (uint32_t)((wn0 + ((l >> 4) & 1) * 8 + (l & 7)) * AROWB
                                      + ((l >> 3) & 1) * 16);
    float acc[2][8][4];
    #pragma unroll
    for (int i = 0; i < 2; i++)
        #pragma unroll
        for (int j = 0; j < 8; j++)
            #pragma unroll
            for (int q = 0; q < 4; q++) acc[i][j][q] = 0.f;
    const int lrow = t >> 2, lseg = t & 3;

    auto load_stage = [&](int s, int buf) {
        uint32_t sa = base + buf * GBUF, sb = base + 4 * GBUF + buf * GBUF;
        #pragma unroll
        for (int i = 0; i < 2; i++) {
            int row = i * 64 + lrow;
            cp_async16(sa + row * AROWB + lseg * 16,
                       (const char*)A2 + ((size_t)(m0 + row) * K2 + s * 32) * 2 + lseg * 16);
        }
        #pragma unroll
        for (int i = 0; i < 2; i++) {
            int row = i * 64 + lrow;
            cp_async16(sb + row * AROWB + lseg * 16,
                       (const char*)Bp + ((size_t)(n0 + row) * K2 + s * 32) * 2 + lseg * 16);
        }
        CP_COMMIT();
    };

    load_stage(0, 0);
    load_stage(1, 1);
    load_stage(2, 2);
    for (int s = 0; s < S; s++) {
        int rem = S - 1 - s;
        if (rem >= 2) { CP_WAIT2(); } else if (rem == 1) { CP_WAIT1(); } else { CP_WAIT0(); }
        __syncthreads();
        if (s + 3 < S) load_stage(s + 3, (s + 3) & 3);
        int buf = s & 3;
        uint32_t sa = base + buf * GBUF, sb = base + 4 * GBUF + buf * GBUF;
        #pragma unroll
        for (int kk = 0; kk < 2; kk++) {
            uint32_t afr[2][4];
            #pragma unroll
            for (int mt = 0; mt < 2; mt++)
                ldsm_x4(afr[mt], sa + aLane + mt * (16 * AROWB) + kk * 32);
            #pragma unroll
            for (int jj = 0; jj < 4; jj++) {
                uint32_t bfr[4];
                ldsm_x4(bfr, sb + bLane + jj * (16 * AROWB) + kk * 32);
                #pragma unroll
                for (int mt = 0; mt < 2; mt++) {
                    mma16816h(acc[mt][2*jj],   afr[mt], bfr);
                    mma16816h(acc[mt][2*jj+1], afr[mt], bfr + 2);
                }
            }
        }
    }
    __syncthreads();
    int g = l >> 2, tig = l & 3;
    int Mtot = gridDim.y * 128;
    #pragma unroll
    for (int mt = 0; mt < 2; mt++) {
        int m1 = m0 + wm0 + mt * 16 + g, m2 = m1 + 8;
        if (l2limit && m1 < l2limit) {
            float ss1 = 0.f, ss2 = 0.f;
            #pragma unroll
            for (int j = 0; j < 8; j++) {
                ss1 += acc[mt][j][0]*acc[mt][j][0] + acc[mt][j][1]*acc[mt][j][1];
                ss2 += acc[mt][j][2]*acc[mt][j][2] + acc[mt][j][3]*acc[mt][j][3];
            }
            ss1 += __shfl_xor_sync(0xffffffffu, ss1, 1);
            ss1 += __shfl_xor_sync(0xffffffffu, ss1, 2);
            ss2 += __shfl_xor_sync(0xffffffffu, ss2, 1);
            ss2 += __shfl_xor_sync(0xffffffffu, ss2, 2);
            float inv1 = 1.f / fmaxf(sqrtf(ss1), 1e-12f);
            float inv2 = 1.f / fmaxf(sqrtf(ss2), 1e-12f);
            #pragma unroll
            for (int j = 0; j < 8; j++) {
                int p = n0 + wn0 + j * 8 + 2 * tig;
                float2 v1, v2;
                v1.x = acc[mt][j][0] * inv1; v1.y = acc[mt][j][1] * inv1;
                v2.x = acc[mt][j][2] * inv2; v2.y = acc[mt][j][3] * inv2;
                *(float2*)&Cp[(size_t)m1 * P + p] = v1;
                *(float2*)&Cp[(size_t)m2 * P + p] = v2;
            }
        } else {
            float bv1 = bias ? bias[m1] : 0.f;
            float bv2 = bias ? bias[m2] : 0.f;
            float s1 = 0.f, q1 = 0.f, s2s = 0.f, q2s = 0.f;
            #pragma unroll
            for (int j = 0; j < 8; j++) {
                int p = n0 + wn0 + j * 8 + 2 * tig;
                size_t o1 = (size_t)m1 * P + p, o2 = (size_t)m2 * P + p;
                float2 v1, v2;
                v1.x = acc[mt][j][0] + bv1; v1.y = acc[mt][j][1] + bv1;
                v2.x = acc[mt][j][2] + bv2; v2.y = acc[mt][j][3] + bv2;
                if (Rp) {
                    float2 r1 = *(const float2*)&Rp[o1];
                    float2 r2 = *(const float2*)&Rp[o2];
                    v1.x += r1.x; v1.y += r1.y; v2.x += r2.x; v2.y += r2.y;
                }
                if (statA) {
                    s1 += v1.x + v1.y; q1 += v1.x * v1.x + v1.y * v1.y;
                    s2s += v2.x + v2.y; q2s += v2.x * v2.x + v2.y * v2.y;
                }
                *(float2*)&Cp[o1] = v1; *(float2*)&Cp[o2] = v2;
            }
            if (statA) {
                s1  += __shfl_xor_sync(0xffffffffu, s1, 1);
                s1  += __shfl_xor_sync(0xffffffffu, s1, 2);
                q1  += __shfl_xor_sync(0xffffffffu, q1, 1);
                q1  += __shfl_xor_sync(0xffffffffu, q1, 2);
                s2s += __shfl_xor_sync(0xffffffffu, s2s, 1);
                s2s += __shfl_xor_sync(0xffffffffu, s2s, 2);
                q2s += __shfl_xor_sync(0xffffffffu, q2s, 1);
                q2s += __shfl_xor_sync(0xffffffffu, q2s, 2);
                if (tig == 0) {
                    atomicAdd(&statA[((size_t)bz * Mtot + m1) * 2],     s1);
                    atomicAdd(&statA[((size_t)bz * Mtot + m1) * 2 + 1], q1);
                    atomicAdd(&statA[((size_t)bz * Mtot + m2) * 2],     s2s);
                    atomicAdd(&statA[((size_t)bz * Mtot + m2) * 2 + 1], q2s);
                }
            }
        }
    }
}

// ---------------- finalize stats ----------------
__global__ void finalize_stats_kernel(const float* __restrict__ A, float* __restrict__ st, int n)
{
    int i = blockIdx.x * blockDim.x + threadIdx.x;
    if (i >= n) return;
    float mean = A[i * 2] * (1.f / P);
    float var  = A[i * 2 + 1] * (1.f / P) - mean * mean;
    st[i * 2] = mean; st[i * 2 + 1] = rsqrtf(var + 1e-5f);
}

// ---------------- parallel probe sums ----------------
__global__ void sums_kernel(const float* __restrict__ qkv,
                            float* __restrict__ qp, float* __restrict__ kh)
{
    int bx = blockIdx.x;
    int bp = bx >> 5, c = bx & 31;
    int b = bp >> 3, head = bp & 7;
    int t = threadIdx.x;
    const float4* qrow = (const float4*)(qkv + ((size_t)(b * 768 + head * 32 + c)) * P);
    const float4* krow = (const float4*)(qkv + ((size_t)(b * 768 + 256 + head * 32 + c)) * P);
    float s = 0.f;
    #pragma unroll
    for (int i = 0; i < 4; i++) { float4 v = qrow[t + 256 * i]; s += v.x + v.y + v.z + v.w; }
    __shared__ float red[256];
    red[t] = s;
    __syncthreads();
    for (int o = 128; o > 0; o >>= 1) { if (t < o) red[t] += red[t + o]; __syncthreads(); }
    if (t == 0) qp[bp * 32 + c] = red[0];
    int h = t >> 2, wq = t & 3;
    float ks = 0.f;
    #pragma unroll
    for (int i = 0; i < 4; i++) { float4 v = krow[h * 16 + wq * 4 + i]; ks += v.x + v.y + v.z + v.w; }
    ks += __shfl_xor_sync(0xffffffffu, ks, 1);
    ks += __shfl_xor_sync(0xffffffffu, ks, 2);
    if (wq == 0) kh[(bp * 32 + c) * 64 + h] = ks;
}

// ---------------- selection + split gather ----------------
__device__ inline void topk16(const float* sc, int* out)
{
    float v[64];
    for (int i = 0; i < 64; i++) v[i] = sc[i];
    for (int k = 0; k < 16; k++) {
        int bi = 0; float bv = v[0];
        for (int i = 1; i < 64; i++) if (v[i] > bv) { bv = v[i]; bi = i; }
        out[k] = bi; v[bi] = -3.0e38f;
    }
}

__global__ void select_gather_kernel(const float* __restrict__ qkv,
                                     const float* __restrict__ qp_g,
                                     const float* __restrict__ kh_g,
                                     __half* __restrict__ ks_o,
                                     __nv_bfloat16* __restrict__ vs_o)
{
    int bp = blockIdx.x;
    int b = bp >> 3, head = bp & 7;
    const float* kb = qkv + ((size_t)(b * 768 + 256 + head * 32)) * P;
    const float* vb = qkv + ((size_t)(b * 768 + 512 + head * 32)) * P;
    __shared__ float s_qp[32];
    __shared__ float s_kh[2048];
    __shared__ float s_sc[64];
    __shared__ int s_ih[16];
    __shared__ int s_iw[16];
    int t = threadIdx.x;
    if (t < 32) s_qp[t] = qp_g[bp * 32 + t];
    for (int i = t; i < 2048; i += 256) s_kh[i] = kh_g[bp * 2048 + i];
    __syncthreads();
    if (t < 64) {
        float s = 0.f;
        for (int c = 0; c < 32; c++) s += s_qp[c] * s_kh[c * 64 + t];
        s_sc[t] = s;
    }
    __syncthreads();
    if (t == 0) topk16(s_sc, s_ih);
    __syncthreads();
    for (int idx = t; idx < 2048; idx += 256) {
        int c = idx >> 6, w = idx & 63;
        float s = 0.f;
        #pragma unroll
        for (int j = 0; j < 16; j++) s += kb[(size_t)c * P + s_ih[j] * 64 + w];
        s_kh[idx] = s;
    }
    __syncthreads();
    if (t < 64) {
        float s = 0.f;
        for (int c = 0; c < 32; c++) s += s_qp[c] * s_kh[c * 64 + t];
        s_sc[t] = s;
    }
    __syncthreads();
    if (t == 0) topk16(s_sc, s_iw);
    __syncthreads();
    __half* ksb = ks_o + (size_t)bp * 8192;
    __nv_bfloat16* vsb = vs_o + (size_t)bp * 16384;
    for (int idx = t; idx < JTOT * 32; idx += 256) {
        int j = idx >> 5, d = idx & 31;
        int jh = j >> 4, jw = j & 15;
        size_t off = (size_t)d * P + s_ih[jh] * 64 + s_iw[jw];
        float kv = kb[off], vv = vb[off];
        ksb[j * 32 + d] = __float2half_rn(kv);
        __nv_bfloat16 vhi = __float2bfloat16_rn(vv);
        __nv_bfloat16 vlo = __float2bfloat16_rn(vv - __bfloat162float(vhi));
        vsb[d * 256 + j] = vhi; vsb[8192 + d * 256 + j] = vlo;
    }
}

// ---------------- HMMA attention (fp16 sim, bf16 PV, hi-only fp16 output) ---------
#define AQHI 0
#define AQLO 10240
#define AKHI 20480
#define AVHI 40960
#define AVLO 57856
#define ATT_SMEM 74752

__global__ void __launch_bounds__(256, 2)
attn_hmma_kernel(const float* __restrict__ qkv,
                 const __half* __restrict__ ks,
                 const __nv_bfloat16* __restrict__ vs,
                 __half* __restrict__ outb, int outStride)
{
    extern __shared__ __align__(16) char sm[];
    uint32_t base = smem_u32(sm);
    int t = threadIdx.x, wid = t >> 5, l = t & 31;
    int bp = blockIdx.y, p0 = blockIdx.x * 128;
    int b = bp >> 3, head = bp & 7;

    const __half* ksrc = ks + (size_t)bp * 8192;
    const __nv_bfloat16* vsrc = vs + (size_t)bp * 16384;
    #pragma unroll
    for (int i = 0; i < 4; i++) {
        int sid = i * 256 + t;
        int row = sid >> 2, s4 = sid & 3;
        cp_async16(base + AKHI + row * 80 + s4 * 16, ksrc + row * 32 + s4 * 8);
    }
    #pragma unroll
    for (int i = 0; i < 8; i++) {
        int sid = i * 256 + t;
        int tile = sid >> 10, rem = sid & 1023, row = rem >> 5, sg = rem & 31;
        cp_async16(base + (tile ? AVLO : AVHI) + row * 528 + sg * 16,
                   vsrc + tile * 8192 + row * 256 + sg * 8);
    }
    CP_COMMIT();

    const float* qb = qkv + ((size_t)(b * 768 + head * 32)) * P;
    #pragma unroll
    for (int i = 0; i < 16; i++) {
        int idx = i * 256 + t;
        int d = idx >> 7, p = idx & 127;
        float f = qb[(size_t)d * P + p0 + p];
        __half hi = __float2half_rn(f);
        __half lo = __float2half_rn(f - __half2float(hi));
        *(__half*)(sm + AQHI + p * 80 + d * 2) = hi;
        *(__half*)(sm + AQLO + p * 80 + d * 2) = lo;
    }
    CP_WAIT0();
    __syncthreads();

    int wm = wid * 16;
    uint32_t aL = (uint32_t)((wm + (l & 15)) * 80 + (l >> 4) * 16);
    uint32_t aq[2][2][4];
    #pragma unroll
    for (int tq = 0; tq < 2; tq++)
        #pragma unroll
        for (int kk = 0; kk < 2; kk++)
            ldsm_x4(aq[tq][kk], base + (tq ? AQLO : AQHI) + aL + kk * 32);

    float accO[4][4];
    #pragma unroll
    for (int i = 0; i < 4; i++)
        #pragma unroll
        for (int q = 0; q < 4; q++) accO[i][q] = 0.f;
    float lsum0 = 0.f, lsum1 = 0.f;
    uint32_t bL = (uint32_t)(((((l >> 4) & 1) * 8) + (l & 7)) * 80 + ((l >> 3) & 1) * 16);
    uint32_t vL = (uint32_t)(((((l >> 4) & 1) * 8) + (l & 7)) * 528 + ((l >> 3) & 1) * 16);

    for (int jc = 0; jc < 4; jc++) {
        float accS[8][4];
        #pragma unroll
        for (int i = 0; i < 8; i++)
            #pragma unroll
            for (int q = 0; q < 4; q++) accS[i][q] = 0.f;
        #pragma unroll
        for (int kk = 0; kk < 2; kk++) {
            #pragma unroll
            for (int nf = 0; nf < 4; nf++) {
                uint32_t rowoff = (uint32_t)((jc * 64 + nf * 16) * 80);
                uint32_t bh[4];
                ldsm_x4(bh, base + AKHI + rowoff + bL + kk * 32);
                mma16816h(accS[2*nf],   aq[0][kk], bh);
                mma16816h(accS[2*nf+1], aq[0][kk], bh + 2);
                mma16816h(accS[2*nf],   aq[1][kk], bh);
                mma16816h(accS[2*nf+1], aq[1][kk], bh + 2);
            }
        }
        #pragma unroll
        for (int k16 = 0; k16 < 4; k16++) {
            float e[8];
            #pragma unroll
            for (int q = 0; q < 4; q++) e[q] = __expf(accS[2*k16][q]);
            #pragma unroll
            for (int q = 0; q < 4; q++) e[4+q] = __expf(accS[2*k16+1][q]);
            lsum0 += e[0] + e[1] + e[4] + e[5];
            lsum1 += e[2] + e[3] + e[6] + e[7];
            uint32_t aPhi[4], aPlo[4];
            #pragma unroll
            for (int q = 0; q < 4; q++) {
                int i0 = (q & 1) * 2 + (q >> 1) * 4;
                float x0 = e[i0], x1 = e[i0 + 1];
                aPhi[q] = packbf2(x0, x1);
                __nv_bfloat162 hh = *(__nv_bfloat162*)&aPhi[q];
                aPlo[q] = packbf2(x0 - __bfloat162float(hh.x), x1 - __bfloat162float(hh.y));
            }
            uint32_t joff = (uint32_t)((jc * 64 + k16 * 16) * 2);
            #pragma unroll
            for (int dn = 0; dn < 2; dn++) {
                uint32_t bvh[4], bvl[4];
                ldsm_x4(bvh, base + AVHI + joff + dn * (16 * 528) + vL);
                ldsm_x4(bvl, base + AVLO + joff + dn * (16 * 528) + vL);
                mma16816(accO[2*dn],   aPhi, bvh);
                mma16816(accO[2*dn+1], aPhi, bvh + 2);
                mma16816(accO[2*dn],   aPhi, bvl);
                mma16816(accO[2*dn+1], aPhi, bvl + 2);
                mma16816(accO[2*dn],   aPlo, bvh);
                mma16816(accO[2*dn+1], aPlo, bvh + 2);
            }
        }
    }

    lsum0 += __shfl_xor_sync(0xffffffffu, lsum0, 1);
    lsum0 += __shfl_xor_sync(0xffffffffu, lsum0, 2);
    lsum1 += __shfl_xor_sync(0xffffffffu, lsum1, 1);
    lsum1 += __shfl_xor_sync(0xffffffffu, lsum1, 2);
    float inv0 = 1.f / lsum0, inv1 = 1.f / lsum1;

    int g = l >> 2, tig = l & 3;
    #pragma unroll
    for (int i = 0; i < 4; i++) {
        #pragma unroll
        for (int q = 0; q < 4; q++) {
            int p = wm + g + ((q < 2) ? 0 : 8);
            int d = i * 8 + 2 * tig + (q & 1);
            float v = accO[i][q] * ((q < 2) ? inv0 : inv1);
            *(__half*)(sm + AQHI + p * 80 + d * 2) = __float2half_rn(v);
        }
    }
    __syncthreads();
    #pragma unroll
    for (int i = 0; i < 2; i++) {
        int sid = i * 256 + t;
        int row = sid >> 2, sh = sid & 3;
        int p = p0 + row;
        size_t rowo = ((size_t)b * P + p) * outStride;
        uint4 v = *(uint4*)(sm + AQHI + row * 80 + sh * 16);
        *(uint4*)(outb + rowo + head * 32 + sh * 8) = v;
    }
}

// ---------------- tiled depthwise 3x3 (+opt input act, +opt output stats) ----------
__global__ void __launch_bounds__(256)
dwconv_kernel(const float* __restrict__ x, const float* __restrict__ w,
              const float* __restrict__ bias, float* __restrict__ y,
              int C, size_t ybstride, float* __restrict__ st,
              const float* __restrict__ stin)
{
    __shared__ float sp[66][68];
    __shared__ float rs[256], rs2[256];
    int plane = blockIdx.x;
    int c = plane % C, b = plane / C;
    int t = threadIdx.x;
    const float* xp = x + ((size_t)b * C + c) * P;

    float im = 0.f, irs = 1.f;
    if (stin) { im = stin[(size_t)plane * 2]; irs = stin[(size_t)plane * 2 + 1]; }

    for (int i = t; i < 260; i += 256) {
        if (i < 66) sp[0][i] = 0.f;
        else if (i < 132) sp[65][i - 66] = 0.f;
        else if (i < 196) sp[i - 132 + 1][0] = 0.f;
        else sp[i - 196 + 1][65] = 0.f;
    }
    const float4* x4 = (const float4*)xp;
    #pragma unroll
    for (int i = 0; i < 4; i++) {
        int idx = i * 256 + t;
        int r = idx >> 4, q = idx & 15;
        float4 v = x4[idx];
        if (stin) {
            v.x = gelu_exact((v.x - im) * irs);
            v.y = gelu_exact((v.y - im) * irs);
            v.z = gelu_exact((v.z - im) * irs);
            v.w = gelu_exact((v.w - im) * irs);
        }
        sp[r + 1][1 + q * 4] = v.x; sp[r + 1][2 + q * 4] = v.y;
        sp[r + 1][3 + q * 4] = v.z; sp[r + 1][4 + q * 4] = v.w;
    }
    __syncthreads();

    const float* wc = w + c * 9;
    float w0 = wc[0], w1 = wc[1], w2 = wc[2], w3 = wc[3], w4 = wc[4];
    float w5 = wc[5], w6 = wc[6], w7 = wc[7], w8 = wc[8];
    float bb = bias[c];
    int th = t >> 4, tw = t & 15;
    int h0 = th * 4, wc0 = tw * 4;
    float out[4][4];
    #pragma unroll
    for (int i = 0; i < 4; i++)
        #pragma unroll
        for (int j = 0; j < 4; j++) out[i][j] = bb;
    #pragma unroll
    for (int dr = 0; dr < 6; dr++) {
        float row[6];
        #pragma unroll
        for (int j = 0; j < 6; j++) row[j] = sp[h0 + dr][wc0 + j];
        #pragma unroll
        for (int r = 0; r < 4; r++) {
            int k = dr - r;
            if (k >= 0 && k < 3) {
                float a0 = (k == 0) ? w0 : ((k == 1) ? w3 : w6);
                float a1 = (k == 0) ? w1 : ((k == 1) ? w4 : w7);
                float a2 = (k == 0) ? w2 : ((k == 1) ? w5 : w8);
                #pragma unroll
                for (int cc = 0; cc < 4; cc++)
                    out[r][cc] += row[cc] * a0 + row[cc + 1] * a1 + row[cc + 2] * a2;
            }
        }
    }
    float* yp = y + (size_t)b * ybstride + (size_t)c * P;
    #pragma unroll
    for (int r = 0; r < 4; r++) {
        float4 o = make_float4(out[r][0], out[r][1], out[r][2], out[r][3]);
        *(float4*)&yp[(h0 + r) * 64 + wc0] = o;
    }
    if (st) {
        float s = 0.f, s2 = 0.f;
        #pragma unroll
        for (int i = 0; i < 4; i++)
            #pragma unroll
            for (int j = 0; j < 4; j++) { float v = out[i][j]; s += v; s2 += v * v; }
        rs[t] = s; rs2[t] = s2;
        __syncthreads();
        for (int o = 128; o > 0; o >>= 1) {
            if (t < o) { rs[t] += rs[t + o]; rs2[t] += rs2[t + o]; }
            __syncthreads();
        }
        if (t == 0) {
            float mean = rs[0] * (1.f / P);
            float var  = rs2[0] * (1.f / P) - mean * mean;
            st[(size_t)plane * 2] = mean;
            st[(size_t)plane * 2 + 1] = rsqrtf(var + 1e-5f);
        }
    }
}

// ---------------- final instnorm using precomputed stats ----------------
__global__ void instnorm_final_kernel(const float* __restrict__ x,
                                      const float* __restrict__ st,
                                      float* __restrict__ y)
{
    size_t blk = blockIdx.x;
    float mean = st[blk * 2], rstd = st[blk * 2 + 1];
    const float4* xp = (const float4*)(x + blk * P);
    float4* yp = (float4*)(y + blk * P);
    for (int i = threadIdx.x; i < P / 4; i += 256) {
        float4 v = xp[i];
        v.x = (v.x - mean) * rstd; v.y = (v.y - mean) * rstd;
        v.z = (v.z - mean) * rstd; v.w = (v.w - mean) * rstd;
        yp[i] = v;
    }
}

// ---------------- host ----------------
extern "C" void kernel_launch(void* const* d_in, const int* in_sizes, int n_in,
                              void* d_out, int out_size)
{
    const float* x      = (const float*)d_in[0];
    const float* ln_g   = (const float*)d_in[1];
    const float* ln_b   = (const float*)d_in[2];
    const float* w_qkv  = (const float*)d_in[3];
    const float* w_out  = (const float*)d_in[4];
    const float* b_out  = (const float*)d_in[5];
    const float* w_dw   = (const float*)d_in[6];
    const float* b_dw   = (const float*)d_in[7];
    const float* w_comb = (const float*)d_in[8];
    const float* b_comb = (const float*)d_in[9];
    const float* w_ff1  = (const float*)d_in[10];
    const float* b_ff1  = (const float*)d_in[11];
    const float* w_ffdw = (const float*)d_in[12];
    const float* b_ffdw = (const float*)d_in[13];
    const float* w_ff2  = (const float*)d_in[14];
    const float* b_ff2  = (const float*)d_in[15];
    (void)in_sizes; (void)n_in; (void)out_size;

    float *qkv, *comb, *h, *r, *f2, *qp, *kh, *pst, *cst, *hst, *fst, *hstA, *fstA;
    __half *wbf, *abf, *ks;
    __nv_bfloat16 *vs;
    cudaGetSymbolAddress((void**)&qkv,  g_qkv);
    cudaGetSymbolAddress((void**)&comb, g_comb);
    cudaGetSymbolAddress((void**)&h,    g_h);
    cudaGetSymbolAddress((void**)&r,    g_r);
    cudaGetSymbolAddress((void**)&f2,   g_f2);
    cudaGetSymbolAddress((void**)&qp,   g_qp);
    cudaGetSymbolAddress((void**)&kh,   g_kh);
    cudaGetSymbolAddress((void**)&pst,  g_pst);
    cudaGetSymbolAddress((void**)&cst,  g_cst);
    cudaGetSymbolAddress((void**)&hst,  g_hst);
    cudaGetSymbolAddress((void**)&fst,  g_fst);
    cudaGetSymbolAddress((void**)&hstA, g_hstA);
    cudaGetSymbolAddress((void**)&fstA, g_fstA);
    cudaGetSymbolAddress((void**)&wbf,  g_wbf);
    cudaGetSymbolAddress((void**)&abf,  g_abf);
    cudaGetSymbolAddress((void**)&ks,   g_ks);
    cudaGetSymbolAddress((void**)&vs,   g_vs);

    const size_t sP = (size_t)P;
    cudaFuncSetAttribute(tc_gemm_kernel, cudaFuncAttributeMaxDynamicSharedMemorySize, GEMM_SMEM);
    cudaFuncSetAttribute(attn_hmma_kernel, cudaFuncAttributeMaxDynamicSharedMemorySize, ATT_SMEM);

    // weight offsets
    const size_t o_qkv = 0;                              // 768 x 512 ([Whi|Whi])
    const size_t o_ao  = o_qkv + (size_t)768 * 512;      // 256 x 512 ([Wf|Wcr] hi)
    const size_t o_ff1 = o_ao  + (size_t)256 * 512;      // 1024 x 256
    const size_t o_ff2 = o_ff1 + (size_t)1024 * 256;     // 256 x 1024

    w_split_kernel<<<768, 256>>>(w_qkv, wbf + o_qkv, 768, 256, 256, 512, 0, 1);    // 0
    ln_stats_kernel<<<128, 256>>>(x, pst);                                         // 1
    ts_split_kernel<<<dim3(64, 8, BATCH), 256>>>(x, abf, 256, 512, 0, 1,
                                                 pst, ln_g, ln_b);                 // 2
    tc_gemm_kernel<<<dim3(32, 6, BATCH), 256, GEMM_SMEM>>>(                        // 3 <- ncu
        wbf + o_qkv, abf, qkv, 512, sP * 512, 768 * sP, 0,
        nullptr, nullptr, nullptr, 512);

    cudaMemsetAsync(hstA, 0, BATCH * FFI * 2 * sizeof(float));
    cudaMemsetAsync(fstA, 0, BATCH * DIM * 2 * sizeof(float));

    sums_kernel<<<2048, 256>>>(qkv, qp, kh);
    select_gather_kernel<<<BP, 256>>>(qkv, qp, kh, ks, vs);
    // attention output: hi-only fp16 into cols [0,256) of 512-stride rows
    attn_hmma_kernel<<<dim3(32, BP), 256, ATT_SMEM>>>(qkv, ks, vs, abf, 512);

    fuse_w_kernel<<<256, 256>>>(w_comb, w_out, b_comb, b_out, kh, qp);
    w_split_kernel<<<256, 256>>>(kh, wbf + o_ao, 256, 256, 256, 512, 0, 0);
    w_split_kernel<<<256, 256>>>(w_comb + 256, wbf + o_ao, 256, 256, 512, 512, 256, 0);

    dwconv_kernel<<<BATCH * 256, 256>>>(x, w_dw, b_dw, comb, 256, 256 * sP,
                                        nullptr, nullptr);
    ts_split_kernel<<<dim3(64, 8, BATCH), 256>>>(comb, abf, 256, 512, 256, 0,
                                                 nullptr, nullptr, nullptr);
    // ao = Wf@attn + Wcr@conv + bfused + x    (K=512, hi-only)
    tc_gemm_kernel<<<dim3(32, 2, BATCH), 256, GEMM_SMEM>>>(
        wbf + o_ao, abf, f2, 512, sP * 512, 256 * sP, 256 * sP,
        qp, x, nullptr, 0);

    w_split_kernel<<<1024, 256>>>(w_ff1, wbf + o_ff1, 1024, 256, 256, 256, 0, 0);
    ts_split_kernel<<<dim3(64, 8, BATCH), 256>>>(f2, abf, 256, 256, 0, 0,
                                                 nullptr, nullptr, nullptr);
    tc_gemm_kernel<<<dim3(32, 8, BATCH), 256, GEMM_SMEM>>>(
        wbf + o_ff1, abf, h, 256, sP * 256, 1024 * sP, 0,
        b_ff1, nullptr, hstA, 0);
    finalize_stats_kernel<<<32, 256>>>(hstA, hst, BATCH * FFI);

    w_split_kernel<<<1024, 256>>>(w_ff2, wbf + o_ff2, 256, 1024, 1024, 1024, 0, 0);
    dwconv_kernel<<<BATCH * FFI, 256>>>(h, w_ffdw, b_ffdw, r, FFI, FFI * sP, cst, hst);
    apply_split_kernel<<<dim3(64, 32, BATCH), 256>>>(r, h, cst, hst, abf);

    tc_gemm_kernel<<<dim3(32, 2, BATCH), 256, GEMM_SMEM>>>(
        wbf + o_ff2, abf, f2, 1024, sP * 1024, 256 * sP, 0,
        b_ff2, nullptr, fstA, 0);
    finalize_stats_kernel<<<8, 256>>>(fstA, fst, BATCH * DIM);

    instnorm_final_kernel<<<BATCH * DIM, 256>>>(f2, fst, (float*)d_out);
}

// round 16
// speedup vs baseline: 1.0656x; 1.0656x over previous
#include <cuda_runtime.h>
#include <cuda_bf16.h>
#include <cuda_fp16.h>
#include <math.h>
#include <stddef.h>
#include <stdint.h>

#define BATCH 8
#define DIM 256
#define P 4096
#define HEADS 8
#define FFI 1024
#define BP 64
#define JTOT 256

__device__ float g_qkv [(size_t)BATCH*768*P];
__device__ float g_comb[(size_t)BATCH*256*P];
__device__ float g_h   [(size_t)BATCH*FFI*P];
__device__ float g_r   [(size_t)BATCH*FFI*P];
__device__ float g_f2  [(size_t)BATCH*DIM*P];
__device__ __half g_wbf [1703936];
__device__ __half g_abf [(size_t)BATCH*P*2048];
__device__ __half g_ks  [(size_t)BP*8192];
__device__ __nv_bfloat16 g_vs [(size_t)BP*16384];
__device__ float g_qp  [BP*32];
__device__ float g_kh  [BP*2048];
__device__ float g_pst [BATCH*P*2];
__device__ float g_cst [BATCH*FFI*2];
__device__ float g_hst [BATCH*FFI*2];
__device__ float g_fst [BATCH*DIM*2];
__device__ float g_hstA[BATCH*FFI*2];
__device__ float g_fstA[BATCH*DIM*2];

__device__ __forceinline__ uint32_t smem_u32(const void* p) {
    uint32_t a;
    asm("{ .reg .u64 t; cvta.to.shared.u64 t, %1; cvt.u32.u64 %0, t; }" : "=r"(a) : "l"(p));
    return a;
}
__device__ __forceinline__ void cp_async16(uint32_t dst, const void* src) {
    asm volatile("cp.async.cg.shared.global [%0], [%1], 16;" :: "r"(dst), "l"(src) : "memory");
}
#define CP_COMMIT() asm volatile("cp.async.commit_group;" ::: "memory")
#define CP_WAIT0()  asm volatile("cp.async.wait_group 0;" ::: "memory")
#define CP_WAIT1()  asm volatile("cp.async.wait_group 1;" ::: "memory")
#define CP_WAIT2()  asm volatile("cp.async.wait_group 2;" ::: "memory")
__device__ __forceinline__ void ldsm_x4(uint32_t* r, uint32_t addr) {
    asm volatile("ldmatrix.sync.aligned.m8n8.x4.shared.b16 {%0,%1,%2,%3}, [%4];"
                 : "=r"(r[0]), "=r"(r[1]), "=r"(r[2]), "=r"(r[3]) : "r"(addr));
}
__device__ __forceinline__ void mma16816h(float* c, const uint32_t* a, const uint32_t* b) {
    asm volatile(
        "mma.sync.aligned.m16n8k16.row.col.f32.f16.f16.f32 "
        "{%0,%1,%2,%3}, {%4,%5,%6,%7}, {%8,%9}, {%0,%1,%2,%3};"
        : "+f"(c[0]), "+f"(c[1]), "+f"(c[2]), "+f"(c[3])
        : "r"(a[0]), "r"(a[1]), "r"(a[2]), "r"(a[3]), "r"(b[0]), "r"(b[1]));
}
__device__ __forceinline__ void mma16816(float* c, const uint32_t* a, const uint32_t* b) {
    asm volatile(
        "mma.sync.aligned.m16n8k16.row.col.f32.bf16.bf16.f32 "
        "{%0,%1,%2,%3}, {%4,%5,%6,%7}, {%8,%9}, {%0,%1,%2,%3};"
        : "+f"(c[0]), "+f"(c[1]), "+f"(c[2]), "+f"(c[3])
        : "r"(a[0]), "r"(a[1]), "r"(a[2]), "r"(a[3]), "r"(b[0]), "r"(b[1]));
}
__device__ __forceinline__ uint32_t packbf2(float a, float b) {
    __nv_bfloat162 h = __floats2bfloat162_rn(a, b);
    return *(uint32_t*)&h;
}
__device__ inline float gelu_exact(float v) {
    return 0.5f * v * (1.0f + erff(v * 0.70710678118654752f));
}

// ---------------- weight split (generalized; dup=1 writes [Whi|Whi]) ----------------
__global__ void w_split_kernel(const float* __restrict__ src, __half* __restrict__ dst,
                               int M, int K, int srcStride, int dstRowStride, int dstColOff,
                               int dup)
{
    int i = blockIdx.x * blockDim.x + threadIdx.x;
    if (i >= M * K) return;
    int m = i / K, k = i - m * K;
    __half hi = __float2half_rn(src[(size_t)m * srcStride + k]);
    size_t row = (size_t)m * dstRowStride + dstColOff;
    dst[row + k] = hi;
    if (dup) dst[row + K + k] = hi;
}

// ---------------- fuse: Wf = Wcl @ w_out, bf = b_comb + Wcl @ b_out ----------------
__global__ void fuse_w_kernel(const float* __restrict__ wcomb, const float* __restrict__ wout,
                              const float* __restrict__ bcomb, const float* __restrict__ bout,
                              float* __restrict__ Wf, float* __restrict__ bf)
{
    int i = blockIdx.x, j = threadIdx.x;
    __shared__ float wrow[256];
    __shared__ float red[256];
    wrow[j] = wcomb[(size_t)i * 512 + j];
    __syncthreads();
    float s = 0.f;
    #pragma unroll 8
    for (int k = 0; k < 256; k++) s += wrow[k] * wout[(size_t)k * 256 + j];
    Wf[(size_t)i * 256 + j] = s;
    red[j] = wrow[j] * bout[j];
    __syncthreads();
    for (int o = 128; o > 0; o >>= 1) {
        if (j < o) red[j] += red[j + o];
        __syncthreads();
    }
    if (j == 0) bf[i] = bcomb[i] + red[0];
}

// ---------------- LN per-pixel stats ----------------
__global__ void ln_stats_kernel(const float* __restrict__ x, float* __restrict__ st)
{
    int idx = blockIdx.x * blockDim.x + threadIdx.x;
    int b = idx >> 12, p = idx & 4095;
    const float* xb = x + (size_t)b * DIM * P + p;
    float s = 0.f, s2 = 0.f;
    #pragma unroll 8
    for (int c = 0; c < DIM; c++) { float v = xb[(size_t)c * P]; s += v; s2 += v * v; }
    float mean = s * (1.f / DIM);
    float var  = s2 * (1.f / DIM) - mean * mean;
    st[idx * 2] = mean; st[idx * 2 + 1] = rsqrtf(var + 1e-5f);
}

// ---------------- transpose+split (writeLo flag, optional LN) ----------------
__global__ void ts_split_kernel(const float* __restrict__ src, __half* __restrict__ dst,
                                int K, int rowStride, int colOff, int writeLo,
                                const float* __restrict__ pst,
                                const float* __restrict__ gamma, const float* __restrict__ beta)
{
    __shared__ float s[32][65];
    int pt = blockIdx.x, kt = blockIdx.y, b = blockIdx.z;
    int t = threadIdx.x;
    const float4* s4 = (const float4*)(src + ((size_t)b * K + kt * 32) * P) + pt * 16;
    int kr = t >> 3, pq = t & 7;
    float4 v0 = s4[(size_t)kr * (P / 4) + pq];
    float4 v1 = s4[(size_t)kr * (P / 4) + pq + 8];
    s[kr][pq*4+0]=v0.x; s[kr][pq*4+1]=v0.y; s[kr][pq*4+2]=v0.z; s[kr][pq*4+3]=v0.w;
    s[kr][32+pq*4+0]=v1.x; s[kr][32+pq*4+1]=v1.y; s[kr][32+pq*4+2]=v1.z; s[kr][32+pq*4+3]=v1.w;
    __syncthreads();
    int pr = t >> 2, ks = t & 3;
    int p = pt * 64 + pr;
    float mean = 0.f, rstd = 1.f;
    if (pst) { mean = pst[((size_t)b*P+p)*2]; rstd = pst[((size_t)b*P+p)*2+1]; }
    __align__(16) __half hi[8];
    __align__(16) __half lo[8];
    #pragma unroll
    for (int i = 0; i < 8; i++) {
        int c = kt * 32 + ks * 8 + i;
        float f = s[ks * 8 + i][pr];
        if (pst) f = (f - mean) * rstd * gamma[c] + beta[c];
        hi[i] = __float2half_rn(f);
        lo[i] = __float2half_rn(f - __half2float(hi[i]));
    }
    __half* dp = dst + ((size_t)b * P + p) * rowStride + colOff + kt * 32 + ks * 8;
    *(uint4*)dp = *(uint4*)hi;
    if (writeLo) *(uint4*)(dp + K) = *(uint4*)lo;
}

// ---------------- gelu(norm(h)) + gelu(norm(r)) -> transposed fp16 (hi only) ------
__global__ void apply_split_kernel(const float* __restrict__ r, const float* __restrict__ h,
                                   const float* __restrict__ str, const float* __restrict__ sth,
                                   __half* __restrict__ dst)
{
    __shared__ float sr[32][65];
    __shared__ float sh[32][65];
    int pt = blockIdx.x, kt = blockIdx.y, b = blockIdx.z;
    int t = threadIdx.x;
    const float4* r4 = (const float4*)(r + ((size_t)b * FFI + kt * 32) * P) + pt * 16;
    const float4* h4 = (const float4*)(h + ((size_t)b * FFI + kt * 32) * P) + pt * 16;
    int kr = t >> 3, pq = t & 7;
    #pragma unroll
    for (int half = 0; half < 2; half++) {
        float4 a = r4[(size_t)kr * (P/4) + pq + half * 8];
        float4 bb = h4[(size_t)kr * (P/4) + pq + half * 8];
        int c0 = half * 32 + pq * 4;
        sr[kr][c0]=a.x; sr[kr][c0+1]=a.y; sr[kr][c0+2]=a.z; sr[kr][c0+3]=a.w;
        sh[kr][c0]=bb.x; sh[kr][c0+1]=bb.y; sh[kr][c0+2]=bb.z; sh[kr][c0+3]=bb.w;
    }
    __syncthreads();
    int pr = t >> 2, ks = t & 3;
    int p = pt * 64 + pr;
    __align__(16) __half hi[8];
    #pragma unroll
    for (int i = 0; i < 8; i++) {
        int c = kt * 32 + ks * 8 + i;
        float mr = str[((size_t)b*FFI+c)*2],  rr = str[((size_t)b*FFI+c)*2+1];
        float mh = sth[((size_t)b*FFI+c)*2],  rh = sth[((size_t)b*FFI+c)*2+1];
        float f = gelu_exact((sh[ks*8+i][pr] - mh) * rh)
                + gelu_exact((sr[ks*8+i][pr] - mr) * rr);
        hi[i] = __float2half_rn(f);
    }
    __half* dp = dst + ((size_t)b * P + p) * 1024 + kt * 32 + ks * 8;
    *(uint4*)dp = *(uint4*)hi;
}

// ---------------- HMMA fp16 GEMM: 32-wide k stages, 4-buffer pipeline ----------------
#define AROWB 80
#define GBUF  10240
#define GEMM_SMEM (8*GBUF)

__global__ void __launch_bounds__(256, 2)
tc_gemm_kernel(const __half* __restrict__ A2, const __half* __restrict__ B2,
               float* __restrict__ C, int K2,
               size_t strideB2, size_t strideC, size_t strideR,
               const float* __restrict__ bias, const float* __restrict__ res,
               float* __restrict__ statA, int l2limit)
{
    extern __shared__ __align__(16) char dyn[];
    const int t = threadIdx.x;
    const int wid = t >> 5, l = t & 31;
    const int n0 = blockIdx.x * 128, m0 = blockIdx.y * 128, bz = blockIdx.z;
    const __half* Bp = B2 + (size_t)bz * strideB2;
    float* Cp = C + (size_t)bz * strideC;
    const float* Rp = res ? res + (size_t)bz * strideR : nullptr;
    const int S = K2 / 32;
    const int wm0 = (wid & 3) * 32, wn0 = (wid >> 2) * 64;
    uint32_t base = smem_u32(dyn);
    const uint32_t aLane = (uint32_t)((wm0 + (l & 15)) * AROWB + (l >> 4) * 16);
    const uint32_t bLane = (uint32_t)((wn0 + ((l >> 4) & 1) * 8 + (l & 7)) * AROWB
                                      + ((l >> 3) & 1) * 16);
    float acc[2][8][4];
    #pragma unroll
    for (int i = 0; i < 2; i++)
        #pragma unroll
        for (int j = 0; j < 8; j++)
            #pragma unroll
            for (int q = 0; q < 4; q++) acc[i][j][q] = 0.f;
    const int lrow = t >> 2, lseg = t & 3;

    auto load_stage = [&](int s, int buf) {
        uint32_t sa = base + buf * GBUF, sb = base + 4 * GBUF + buf * GBUF;
        #pragma unroll
        for (int i = 0; i < 2; i++) {
            int row = i * 64 + lrow;
            cp_async16(sa + row * AROWB + lseg * 16,
                       (const char*)A2 + ((size_t)(m0 + row) * K2 + s * 32) * 2 + lseg * 16);
        }
        #pragma unroll
        for (int i = 0; i < 2; i++) {
            int row = i * 64 + lrow;
            cp_async16(sb + row * AROWB + lseg * 16,
                       (const char*)Bp + ((size_t)(n0 + row) * K2 + s * 32) * 2 + lseg * 16);
        }
        CP_COMMIT();
    };

    load_stage(0, 0);
    load_stage(1, 1);
    load_stage(2, 2);
    for (int s = 0; s < S; s++) {
        int rem = S - 1 - s;
        if (rem >= 2) { CP_WAIT2(); } else if (rem == 1) { CP_WAIT1(); } else { CP_WAIT0(); }
        __syncthreads();
        if (s + 3 < S) load_stage(s + 3, (s + 3) & 3);
        int buf = s & 3;
        uint32_t sa = base + buf * GBUF, sb = base + 4 * GBUF + buf * GBUF;
        #pragma unroll
        for (int kk = 0; kk < 2; kk++) {
            uint32_t afr[2][4];
            #pragma unroll
            for (int mt = 0; mt < 2; mt++)
                ldsm_x4(afr[mt], sa + aLane + mt * (16 * AROWB) + kk * 32);
            #pragma unroll
            for (int jj = 0; jj < 4; jj++) {
                uint32_t bfr[4];
                ldsm_x4(bfr, sb + bLane + jj * (16 * AROWB) + kk * 32);
                #pragma unroll
                for (int mt = 0; mt < 2; mt++) {
                    mma16816h(acc[mt][2*jj],   afr[mt], bfr);
                    mma16816h(acc[mt][2*jj+1], afr[mt], bfr + 2);
                }
            }
        }
    }
    __syncthreads();
    int g = l >> 2, tig = l & 3;
    int Mtot = gridDim.y * 128;
    #pragma unroll
    for (int mt = 0; mt < 2; mt++) {
        int m1 = m0 + wm0 + mt * 16 + g, m2 = m1 + 8;
        if (l2limit && m1 < l2limit) {
            float ss1 = 0.f, ss2 = 0.f;
            #pragma unroll
            for (int j = 0; j < 8; j++) {
                ss1 += acc[mt][j][0]*acc[mt][j][0] + acc[mt][j][1]*acc[mt][j][1];
                ss2 += acc[mt][j][2]*acc[mt][j][2] + acc[mt][j][3]*acc[mt][j][3];
            }
            ss1 += __shfl_xor_sync(0xffffffffu, ss1, 1);
            ss1 += __shfl_xor_sync(0xffffffffu, ss1, 2);
            ss2 += __shfl_xor_sync(0xffffffffu, ss2, 1);
            ss2 += __shfl_xor_sync(0xffffffffu, ss2, 2);
            float inv1 = 1.f / fmaxf(sqrtf(ss1), 1e-12f);
            float inv2 = 1.f / fmaxf(sqrtf(ss2), 1e-12f);
            #pragma unroll
            for (int j = 0; j < 8; j++) {
                int p = n0 + wn0 + j * 8 + 2 * tig;
                float2 v1, v2;
                v1.x = acc[mt][j][0] * inv1; v1.y = acc[mt][j][1] * inv1;
                v2.x = acc[mt][j][2] * inv2; v2.y = acc[mt][j][3] * inv2;
                *(float2*)&Cp[(size_t)m1 * P + p] = v1;
                *(float2*)&Cp[(size_t)m2 * P + p] = v2;
            }
        } else {
            float bv1 = bias ? bias[m1] : 0.f;
            float bv2 = bias ? bias[m2] : 0.f;
            float s1 = 0.f, q1 = 0.f, s2s = 0.f, q2s = 0.f;
            #pragma unroll
            for (int j = 0; j < 8; j++) {
                int p = n0 + wn0 + j * 8 + 2 * tig;
                size_t o1 = (size_t)m1 * P + p, o2 = (size_t)m2 * P + p;
                float2 v1, v2;
                v1.x = acc[mt][j][0] + bv1; v1.y = acc[mt][j][1] + bv1;
                v2.x = acc[mt][j][2] + bv2; v2.y = acc[mt][j][3] + bv2;
                if (Rp) {
                    float2 r1 = *(const float2*)&Rp[o1];
                    float2 r2 = *(const float2*)&Rp[o2];
                    v1.x += r1.x; v1.y += r1.y; v2.x += r2.x; v2.y += r2.y;
                }
                if (statA) {
                    s1 += v1.x + v1.y; q1 += v1.x * v1.x + v1.y * v1.y;
                    s2s += v2.x + v2.y; q2s += v2.x * v2.x + v2.y * v2.y;
                }
                *(float2*)&Cp[o1] = v1; *(float2*)&Cp[o2] = v2;
            }
            if (statA) {
                s1  += __shfl_xor_sync(0xffffffffu, s1, 1);
                s1  += __shfl_xor_sync(0xffffffffu, s1, 2);
                q1  += __shfl_xor_sync(0xffffffffu, q1, 1);
                q1  += __shfl_xor_sync(0xffffffffu, q1, 2);
                s2s += __shfl_xor_sync(0xffffffffu, s2s, 1);
                s2s += __shfl_xor_sync(0xffffffffu, s2s, 2);
                q2s += __shfl_xor_sync(0xffffffffu, q2s, 1);
                q2s += __shfl_xor_sync(0xffffffffu, q2s, 2);
                if (tig == 0) {
                    atomicAdd(&statA[((size_t)bz * Mtot + m1) * 2],     s1);
                    atomicAdd(&statA[((size_t)bz * Mtot + m1) * 2 + 1], q1);
                    atomicAdd(&statA[((size_t)bz * Mtot + m2) * 2],     s2s);
                    atomicAdd(&statA[((size_t)bz * Mtot + m2) * 2 + 1], q2s);
                }
            }
        }
    }
}

// ---------------- finalize stats ----------------
__global__ void finalize_stats_kernel(const float* __restrict__ A, float* __restrict__ st, int n)
{
    int i = blockIdx.x * blockDim.x + threadIdx.x;
    if (i >= n) return;
    float mean = A[i * 2] * (1.f / P);
    float var  = A[i * 2 + 1] * (1.f / P) - mean * mean;
    st[i * 2] = mean; st[i * 2 + 1] = rsqrtf(var + 1e-5f);
}

// ---------------- parallel probe sums ----------------
__global__ void sums_kernel(const float* __restrict__ qkv,
                            float* __restrict__ qp, float* __restrict__ kh)
{
    int bx = blockIdx.x;
    int bp = bx >> 5, c = bx & 31;
    int b = bp >> 3, head = bp & 7;
    int t = threadIdx.x;
    const float4* qrow = (const float4*)(qkv + ((size_t)(b * 768 + head * 32 + c)) * P);
    const float4* krow = (const float4*)(qkv + ((size_t)(b * 768 + 256 + head * 32 + c)) * P);
    float s = 0.f;
    #pragma unroll
    for (int i = 0; i < 4; i++) { float4 v = qrow[t + 256 * i]; s += v.x + v.y + v.z + v.w; }
    __shared__ float red[256];
    red[t] = s;
    __syncthreads();
    for (int o = 128; o > 0; o >>= 1) { if (t < o) red[t] += red[t + o]; __syncthreads(); }
    if (t == 0) qp[bp * 32 + c] = red[0];
    int h = t >> 2, wq = t & 3;
    float ks = 0.f;
    #pragma unroll
    for (int i = 0; i < 4; i++) { float4 v = krow[h * 16 + wq * 4 + i]; ks += v.x + v.y + v.z + v.w; }
    ks += __shfl_xor_sync(0xffffffffu, ks, 1);
    ks += __shfl_xor_sync(0xffffffffu, ks, 2);
    if (wq == 0) kh[(bp * 32 + c) * 64 + h] = ks;
}

// ---------------- selection + split gather ----------------
__device__ inline void topk16(const float* sc, int* out)
{
    float v[64];
    for (int i = 0; i < 64; i++) v[i] = sc[i];
    for (int k = 0; k < 16; k++) {
        int bi = 0; float bv = v[0];
        for (int i = 1; i < 64; i++) if (v[i] > bv) { bv = v[i]; bi = i; }
        out[k] = bi; v[bi] = -3.0e38f;
    }
}

__global__ void select_gather_kernel(const float* __restrict__ qkv,
                                     const float* __restrict__ qp_g,
                                     const float* __restrict__ kh_g,
                                     __half* __restrict__ ks_o,
                                     __nv_bfloat16* __restrict__ vs_o)
{
    int bp = blockIdx.x;
    int b = bp >> 3, head = bp & 7;
    const float* kb = qkv + ((size_t)(b * 768 + 256 + head * 32)) * P;
    const float* vb = qkv + ((size_t)(b * 768 + 512 + head * 32)) * P;
    __shared__ float s_qp[32];
    __shared__ float s_kh[2048];
    __shared__ float s_sc[64];
    __shared__ int s_ih[16];
    __shared__ int s_iw[16];
    int t = threadIdx.x;
    if (t < 32) s_qp[t] = qp_g[bp * 32 + t];
    for (int i = t; i < 2048; i += 256) s_kh[i] = kh_g[bp * 2048 + i];
    __syncthreads();
    if (t < 64) {
        float s = 0.f;
        for (int c = 0; c < 32; c++) s += s_qp[c] * s_kh[c * 64 + t];
        s_sc[t] = s;
    }
    __syncthreads();
    if (t == 0) topk16(s_sc, s_ih);
    __syncthreads();
    for (int idx = t; idx < 2048; idx += 256) {
        int c = idx >> 6, w = idx & 63;
        float s = 0.f;
        #pragma unroll
        for (int j = 0; j < 16; j++) s += kb[(size_t)c * P + s_ih[j] * 64 + w];
        s_kh[idx] = s;
    }
    __syncthreads();
    if (t < 64) {
        float s = 0.f;
        for (int c = 0; c < 32; c++) s += s_qp[c] * s_kh[c * 64 + t];
        s_sc[t] = s;
    }
    __syncthreads();
    if (t == 0) topk16(s_sc, s_iw);
    __syncthreads();
    __half* ksb = ks_o + (size_t)bp * 8192;
    __nv_bfloat16* vsb = vs_o + (size_t)bp * 16384;
    for (int idx = t; idx < JTOT * 32; idx += 256) {
        int j = idx >> 5, d = idx & 31;
        int jh = j >> 4, jw = j & 15;
        size_t off = (size_t)d * P + s_ih[jh] * 64 + s_iw[jw];
        float kv = kb[off], vv = vb[off];
        ksb[j * 32 + d] = __float2half_rn(kv);
        __nv_bfloat16 vhi = __float2bfloat16_rn(vv);
        __nv_bfloat16 vlo = __float2bfloat16_rn(vv - __bfloat162float(vhi));
        vsb[d * 256 + j] = vhi; vsb[8192 + d * 256 + j] = vlo;
    }
}

// ---------------- HMMA attention (fp16 sim, bf16 PV, hi-only fp16 output) ---------
#define AQHI 0
#define AQLO 10240
#define AKHI 20480
#define AVHI 40960
#define AVLO 57856
#define ATT_SMEM 74752

__global__ void __launch_bounds__(256, 2)
attn_hmma_kernel(const float* __restrict__ qkv,
                 const __half* __restrict__ ks,
                 const __nv_bfloat16* __restrict__ vs,
                 __half* __restrict__ outb, int outStride)
{
    extern __shared__ __align__(16) char sm[];
    uint32_t base = smem_u32(sm);
    int t = threadIdx.x, wid = t >> 5, l = t & 31;
    int bp = blockIdx.y, p0 = blockIdx.x * 128;
    int b = bp >> 3, head = bp & 7;

    const __half* ksrc = ks + (size_t)bp * 8192;
    const __nv_bfloat16* vsrc = vs + (size_t)bp * 16384;
    #pragma unroll
    for (int i = 0; i < 4; i++) {
        int sid = i * 256 + t;
        int row = sid >> 2, s4 = sid & 3;
        cp_async16(base + AKHI + row * 80 + s4 * 16, ksrc + row * 32 + s4 * 8);
    }
    #pragma unroll
    for (int i = 0; i < 8; i++) {
        int sid = i * 256 + t;
        int tile = sid >> 10, rem = sid & 1023, row = rem >> 5, sg = rem & 31;
        cp_async16(base + (tile ? AVLO : AVHI) + row * 528 + sg * 16,
                   vsrc + tile * 8192 + row * 256 + sg * 8);
    }
    CP_COMMIT();

    const float* qb = qkv + ((size_t)(b * 768 + head * 32)) * P;
    #pragma unroll
    for (int i = 0; i < 16; i++) {
        int idx = i * 256 + t;
        int d = idx >> 7, p = idx & 127;
        float f = qb[(size_t)d * P + p0 + p];
        __half hi = __float2half_rn(f);
        __half lo = __float2half_rn(f - __half2float(hi));
        *(__half*)(sm + AQHI + p * 80 + d * 2) = hi;
        *(__half*)(sm + AQLO + p * 80 + d * 2) = lo;
    }
    CP_WAIT0();
    __syncthreads();

    int wm = wid * 16;
    uint32_t aL = (uint32_t)((wm + (l & 15)) * 80 + (l >> 4) * 16);
    uint32_t aq[2][2][4];
    #pragma unroll
    for (int tq = 0; tq < 2; tq++)
        #pragma unroll
        for (int kk = 0; kk < 2; kk++)
            ldsm_x4(aq[tq][kk], base + (tq ? AQLO : AQHI) + aL + kk * 32);

    float accO[4][4];
    #pragma unroll
    for (int i = 0; i < 4; i++)
        #pragma unroll
        for (int q = 0; q < 4; q++) accO[i][q] = 0.f;
    float lsum0 = 0.f, lsum1 = 0.f;
    uint32_t bL = (uint32_t)(((((l >> 4) & 1) * 8) + (l & 7)) * 80 + ((l >> 3) & 1) * 16);
    uint32_t vL = (uint32_t)(((((l >> 4) & 1) * 8) + (l & 7)) * 528 + ((l >> 3) & 1) * 16);

    for (int jc = 0; jc < 4; jc++) {
        float accS[8][4];
        #pragma unroll
        for (int i = 0; i < 8; i++)
            #pragma unroll
            for (int q = 0; q < 4; q++) accS[i][q] = 0.f;
        #pragma unroll
        for (int kk = 0; kk < 2; kk++) {
            #pragma unroll
            for (int nf = 0; nf < 4; nf++) {
                uint32_t rowoff = (uint32_t)((jc * 64 + nf * 16) * 80);
                uint32_t bh[4];
                ldsm_x4(bh, base + AKHI + rowoff + bL + kk * 32);
                mma16816h(accS[2*nf],   aq[0][kk], bh);
                mma16816h(accS[2*nf+1], aq[0][kk], bh + 2);
                mma16816h(accS[2*nf],   aq[1][kk], bh);
                mma16816h(accS[2*nf+1], aq[1][kk], bh + 2);
            }
        }
        #pragma unroll
        for (int k16 = 0; k16 < 4; k16++) {
            float e[8];
            #pragma unroll
            for (int q = 0; q < 4; q++) e[q] = __expf(accS[2*k16][q]);
            #pragma unroll
            for (int q = 0; q < 4; q++) e[4+q] = __expf(accS[2*k16+1][q]);
            lsum0 += e[0] + e[1] + e[4] + e[5];
            lsum1 += e[2] + e[3] + e[6] + e[7];
            uint32_t aPhi[4], aPlo[4];
            #pragma unroll
            for (int q = 0; q < 4; q++) {
                int i0 = (q & 1) * 2 + (q >> 1) * 4;
                float x0 = e[i0], x1 = e[i0 + 1];
                aPhi[q] = packbf2(x0, x1);
                __nv_bfloat162 hh = *(__nv_bfloat162*)&aPhi[q];
                aPlo[q] = packbf2(x0 - __bfloat162float(hh.x), x1 - __bfloat162float(hh.y));
            }
            uint32_t joff = (uint32_t)((jc * 64 + k16 * 16) * 2);
            #pragma unroll
            for (int dn = 0; dn < 2; dn++) {
                uint32_t bvh[4], bvl[4];
                ldsm_x4(bvh, base + AVHI + joff + dn * (16 * 528) + vL);
                ldsm_x4(bvl, base + AVLO + joff + dn * (16 * 528) + vL);
                mma16816(accO[2*dn],   aPhi, bvh);
                mma16816(accO[2*dn+1], aPhi, bvh + 2);
                mma16816(accO[2*dn],   aPhi, bvl);
                mma16816(accO[2*dn+1], aPhi, bvl + 2);
                mma16816(accO[2*dn],   aPlo, bvh);
                mma16816(accO[2*dn+1], aPlo, bvh + 2);
            }
        }
    }

    lsum0 += __shfl_xor_sync(0xffffffffu, lsum0, 1);
    lsum0 += __shfl_xor_sync(0xffffffffu, lsum0, 2);
    lsum1 += __shfl_xor_sync(0xffffffffu, lsum1, 1);
    lsum1 += __shfl_xor_sync(0xffffffffu, lsum1, 2);
    float inv0 = 1.f / lsum0, inv1 = 1.f / lsum1;

    int g = l >> 2, tig = l & 3;
    #pragma unroll
    for (int i = 0; i < 4; i++) {
        #pragma unroll
        for (int q = 0; q < 4; q++) {
            int p = wm + g + ((q < 2) ? 0 : 8);
            int d = i * 8 + 2 * tig + (q & 1);
            float v = accO[i][q] * ((q < 2) ? inv0 : inv1);
            *(__half*)(sm + AQHI + p * 80 + d * 2) = __float2half_rn(v);
        }
    }
    __syncthreads();
    #pragma unroll
    for (int i = 0; i < 2; i++) {
        int sid = i * 256 + t;
        int row = sid >> 2, sh = sid & 3;
        int p = p0 + row;
        size_t rowo = ((size_t)b * P + p) * outStride;
        uint4 v = *(uint4*)(sm + AQHI + row * 80 + sh * 16);
        *(uint4*)(outb + rowo + head * 32 + sh * 8) = v;
    }
}

// ---------------- tiled depthwise 3x3 (+opt input act, +opt output stats) ----------
__global__ void __launch_bounds__(256)
dwconv_kernel(const float* __restrict__ x, const float* __restrict__ w,
              const float* __restrict__ bias, float* __restrict__ y,
              int C, size_t ybstride, float* __restrict__ st,
              const float* __restrict__ stin)
{
    __shared__ float sp[66][68];
    __shared__ float rs[256], rs2[256];
    int plane = blockIdx.x;
    int c = plane % C, b = plane / C;
    int t = threadIdx.x;
    const float* xp = x + ((size_t)b * C + c) * P;

    float im = 0.f, irs = 1.f;
    if (stin) { im = stin[(size_t)plane * 2]; irs = stin[(size_t)plane * 2 + 1]; }

    for (int i = t; i < 260; i += 256) {
        if (i < 66) sp[0][i] = 0.f;
        else if (i < 132) sp[65][i - 66] = 0.f;
        else if (i < 196) sp[i - 132 + 1][0] = 0.f;
        else sp[i - 196 + 1][65] = 0.f;
    }
    const float4* x4 = (const float4*)xp;
    #pragma unroll
    for (int i = 0; i < 4; i++) {
        int idx = i * 256 + t;
        int r = idx >> 4, q = idx & 15;
        float4 v = x4[idx];
        if (stin) {
            v.x = gelu_exact((v.x - im) * irs);
            v.y = gelu_exact((v.y - im) * irs);
            v.z = gelu_exact((v.z - im) * irs);
            v.w = gelu_exact((v.w - im) * irs);
        }
        sp[r + 1][1 + q * 4] = v.x; sp[r + 1][2 + q * 4] = v.y;
        sp[r + 1][3 + q * 4] = v.z; sp[r + 1][4 + q * 4] = v.w;
    }
    __syncthreads();

    const float* wc = w + c * 9;
    float w0 = wc[0], w1 = wc[1], w2 = wc[2], w3 = wc[3], w4 = wc[4];
    float w5 = wc[5], w6 = wc[6], w7 = wc[7], w8 = wc[8];
    float bb = bias[c];
    int th = t >> 4, tw = t & 15;
    int h0 = th * 4, wc0 = tw * 4;
    float out[4][4];
    #pragma unroll
    for (int i = 0; i < 4; i++)
        #pragma unroll
        for (int j = 0; j < 4; j++) out[i][j] = bb;
    #pragma unroll
    for (int dr = 0; dr < 6; dr++) {
        float row[6];
        #pragma unroll
        for (int j = 0; j < 6; j++) row[j] = sp[h0 + dr][wc0 + j];
        #pragma unroll
        for (int r = 0; r < 4; r++) {
            int k = dr - r;
            if (k >= 0 && k < 3) {
                float a0 = (k == 0) ? w0 : ((k == 1) ? w3 : w6);
                float a1 = (k == 0) ? w1 : ((k == 1) ? w4 : w7);
                float a2 = (k == 0) ? w2 : ((k == 1) ? w5 : w8);
                #pragma unroll
                for (int cc = 0; cc < 4; cc++)
                    out[r][cc] += row[cc] * a0 + row[cc + 1] * a1 + row[cc + 2] * a2;
            }
        }
    }
    float* yp = y + (size_t)b * ybstride + (size_t)c * P;
    #pragma unroll
    for (int r = 0; r < 4; r++) {
        float4 o = make_float4(out[r][0], out[r][1], out[r][2], out[r][3]);
        *(float4*)&yp[(h0 + r) * 64 + wc0] = o;
    }
    if (st) {
        float s = 0.f, s2 = 0.f;
        #pragma unroll
        for (int i = 0; i < 4; i++)
            #pragma unroll
            for (int j = 0; j < 4; j++) { float v = out[i][j]; s += v; s2 += v * v; }
        rs[t] = s; rs2[t] = s2;
        __syncthreads();
        for (int o = 128; o > 0; o >>= 1) {
            if (t < o) { rs[t] += rs[t + o]; rs2[t] += rs2[t + o]; }
            __syncthreads();
        }
        if (t == 0) {
            float mean = rs[0] * (1.f / P);
            float var  = rs2[0] * (1.f / P) - mean * mean;
            st[(size_t)plane * 2] = mean;
            st[(size_t)plane * 2 + 1] = rsqrtf(var + 1e-5f);
        }
    }
}

// ---------------- final instnorm using precomputed stats ----------------
__global__ void instnorm_final_kernel(const float* __restrict__ x,
                                      const float* __restrict__ st,
                                      float* __restrict__ y)
{
    size_t blk = blockIdx.x;
    float mean = st[blk * 2], rstd = st[blk * 2 + 1];
    const float4* xp = (const float4*)(x + blk * P);
    float4* yp = (float4*)(y + blk * P);
    for (int i = threadIdx.x; i < P / 4; i += 256) {
        float4 v = xp[i];
        v.x = (v.x - mean) * rstd; v.y = (v.y - mean) * rstd;
        v.z = (v.z - mean) * rstd; v.w = (v.w - mean) * rstd;
        yp[i] = v;
    }
}

// ---------------- host ----------------
extern "C" void kernel_launch(void* const* d_in, const int* in_sizes, int n_in,
                              void* d_out, int out_size)
{
    const float* x      = (const float*)d_in[0];
    const float* ln_g   = (const float*)d_in[1];
    const float* ln_b   = (const float*)d_in[2];
    const float* w_qkv  = (const float*)d_in[3];
    const float* w_out  = (const float*)d_in[4];
    const float* b_out  = (const float*)d_in[5];
    const float* w_dw   = (const float*)d_in[6];
    const float* b_dw   = (const float*)d_in[7];
    const float* w_comb = (const float*)d_in[8];
    const float* b_comb = (const float*)d_in[9];
    const float* w_ff1  = (const float*)d_in[10];
    const float* b_ff1  = (const float*)d_in[11];
    const float* w_ffdw = (const float*)d_in[12];
    const float* b_ffdw = (const float*)d_in[13];
    const float* w_ff2  = (const float*)d_in[14];
    const float* b_ff2  = (const float*)d_in[15];
    (void)in_sizes; (void)n_in; (void)out_size;

    float *qkv, *comb, *h, *r, *f2, *qp, *kh, *pst, *cst, *hst, *fst, *hstA, *fstA;
    __half *wbf, *abf, *ks;
    __nv_bfloat16 *vs;
    cudaGetSymbolAddress((void**)&qkv,  g_qkv);
    cudaGetSymbolAddress((void**)&comb, g_comb);
    cudaGetSymbolAddress((void**)&h,    g_h);
    cudaGetSymbolAddress((void**)&r,    g_r);
    cudaGetSymbolAddress((void**)&f2,   g_f2);
    cudaGetSymbolAddress((void**)&qp,   g_qp);
    cudaGetSymbolAddress((void**)&kh,   g_kh);
    cudaGetSymbolAddress((void**)&pst,  g_pst);
    cudaGetSymbolAddress((void**)&cst,  g_cst);
    cudaGetSymbolAddress((void**)&hst,  g_hst);
    cudaGetSymbolAddress((void**)&fst,  g_fst);
    cudaGetSymbolAddress((void**)&hstA, g_hstA);
    cudaGetSymbolAddress((void**)&fstA, g_fstA);
    cudaGetSymbolAddress((void**)&wbf,  g_wbf);
    cudaGetSymbolAddress((void**)&abf,  g_abf);
    cudaGetSymbolAddress((void**)&ks,   g_ks);
    cudaGetSymbolAddress((void**)&vs,   g_vs);

    const size_t sP = (size_t)P;
    cudaFuncSetAttribute(tc_gemm_kernel, cudaFuncAttributeMaxDynamicSharedMemorySize, GEMM_SMEM);
    cudaFuncSetAttribute(attn_hmma_kernel, cudaFuncAttributeMaxDynamicSharedMemorySize, ATT_SMEM);

    // weight offsets (all hi-only now)
    const size_t o_qkv = 0;                              // 768 x 256
    const size_t o_ao  = o_qkv + (size_t)768 * 256;      // 256 x 512 ([Wf|Wcr] hi)
    const size_t o_ff1 = o_ao  + (size_t)256 * 512;      // 1024 x 256
    const size_t o_ff2 = o_ff1 + (size_t)1024 * 256;     // 256 x 1024

    w_split_kernel<<<768, 256>>>(w_qkv, wbf + o_qkv, 768, 256, 256, 256, 0, 0);    // 0
    ln_stats_kernel<<<128, 256>>>(x, pst);                                         // 1
    ts_split_kernel<<<dim3(64, 8, BATCH), 256>>>(x, abf, 256, 256, 0, 0,
                                                 pst, ln_g, ln_b);                 // 2
    tc_gemm_kernel<<<dim3(32, 6, BATCH), 256, GEMM_SMEM>>>(                        // 3 <- ncu
        wbf + o_qkv, abf, qkv, 256, sP * 256, 768 * sP, 0,
        nullptr, nullptr, nullptr, 512);

    cudaMemsetAsync(hstA, 0, BATCH * FFI * 2 * sizeof(float));
    cudaMemsetAsync(fstA, 0, BATCH * DIM * 2 * sizeof(float));

    sums_kernel<<<2048, 256>>>(qkv, qp, kh);
    select_gather_kernel<<<BP, 256>>>(qkv, qp, kh, ks, vs);
    // attention output: hi-only fp16 into cols [0,256) of 512-stride rows
    attn_hmma_kernel<<<dim3(32, BP), 256, ATT_SMEM>>>(qkv, ks, vs, abf, 512);

    fuse_w_kernel<<<256, 256>>>(w_comb, w_out, b_comb, b_out, kh, qp);
    w_split_kernel<<<256, 256>>>(kh, wbf + o_ao, 256, 256, 256, 512, 0, 0);
    w_split_kernel<<<256, 256>>>(w_comb + 256, wbf + o_ao, 256, 256, 512, 512, 256, 0);

    dwconv_kernel<<<BATCH * 256, 256>>>(x, w_dw, b_dw, comb, 256, 256 * sP,
                                        nullptr, nullptr);
    ts_split_kernel<<<dim3(64, 8, BATCH), 256>>>(comb, abf, 256, 512, 256, 0,
                                                 nullptr, nullptr, nullptr);
    // ao = Wf@attn + Wcr@conv + bfused + x    (K=512, hi-only)
    tc_gemm_kernel<<<dim3(32, 2, BATCH), 256, GEMM_SMEM>>>(
        wbf + o_ao, abf, f2, 512, sP * 512, 256 * sP, 256 * sP,
        qp, x, nullptr, 0);

    w_split_kernel<<<1024, 256>>>(w_ff1, wbf + o_ff1, 1024, 256, 256, 256, 0, 0);
    ts_split_kernel<<<dim3(64, 8, BATCH), 256>>>(f2, abf, 256, 256, 0, 0,
                                                 nullptr, nullptr, nullptr);
    tc_gemm_kernel<<<dim3(32, 8, BATCH), 256, GEMM_SMEM>>>(
        wbf + o_ff1, abf, h, 256, sP * 256, 1024 * sP, 0,
        b_ff1, nullptr, hstA, 0);
    finalize_stats_kernel<<<32, 256>>>(hstA, hst, BATCH * FFI);

    w_split_kernel<<<1024, 256>>>(w_ff2, wbf + o_ff2, 256, 1024, 1024, 1024, 0, 0);
    dwconv_kernel<<<BATCH * FFI, 256>>>(h, w_ffdw, b_ffdw, r, FFI, FFI * sP, cst, hst);
    apply_split_kernel<<<dim3(64, 32, BATCH), 256>>>(r, h, cst, hst, abf);

    tc_gemm_kernel<<<dim3(32, 2, BATCH), 256, GEMM_SMEM>>>(
        wbf + o_ff2, abf, f2, 1024, sP * 1024, 256 * sP, 0,
        b_ff2, nullptr, fstA, 0);
    finalize_stats_kernel<<<8, 256>>>(fstA, fst, BATCH * DIM);

    instnorm_final_kernel<<<BATCH * DIM, 256>>>(f2, fst, (float*)d_out);
}